// round 1
// baseline (speedup 1.0000x reference)
#include <cuda_runtime.h>
#include <math.h>

#define SEQ 8192
#define DM 1024
#define NH 16
#define DH 64
#define NN (NH*DH)   // 1024

// Scratch (device globals; no allocation allowed in kernel_launch)
__device__ float g_kact[SEQ * NN];   // act(k) = elu(k)+1
__device__ float g_v[SEQ * NN];      // v projection
__device__ float g_a[SEQ * NH];      // a[t,h] = sum_d act(k[t,h,d])
__device__ float g_rden[SEQ * NH];   // 1 / cumsum(a)
__device__ float g_attn[SEQ * NN];   // attention output (pre-MLP)
__device__ float g_h1[SEQ * DM];     // gelu(attn @ w1^T + b1)

// ---------------------------------------------------------------------------
// GEMM: C[M,N] = A[M,K] @ B[N,K]^T  (both row-major; B stored as [N,K])
// 128x128 block tile, 8-deep K panel, 8x8 per-thread microtile, 256 threads.
// EPI: 0=none, 1=elu(x)+1, 2=gelu(x+bias), 3=x+bias
// ---------------------------------------------------------------------------
template<int EPI>
__global__ __launch_bounds__(256, 2)
void gemm_tn(const float* __restrict__ A, const float* __restrict__ B,
             const float* __restrict__ bias, float* __restrict__ C,
             int M, int N, int K)
{
    __shared__ float As[8][128];
    __shared__ float Bs[8][128];

    const int bm = blockIdx.y * 128;
    const int bn = blockIdx.x * 128;
    const int tid = threadIdx.x;

    // global->smem staging: each thread loads one float4 of A and one of B
    const int lr = tid >> 1;          // 0..127 tile row
    const int lc = (tid & 1) << 2;    // 0 or 4 (k offset)
    // microtile mapping
    const int tm = (tid >> 4) << 3;   // 0..120 step 8
    const int tn = (tid & 15) << 3;   // 0..120 step 8

    const float* Aptr = A + (size_t)(bm + lr) * K + lc;
    const float* Bptr = B + (size_t)(bn + lr) * K + lc;

    float acc[8][8];
#pragma unroll
    for (int i = 0; i < 8; i++)
#pragma unroll
        for (int j = 0; j < 8; j++) acc[i][j] = 0.f;

    for (int k0 = 0; k0 < K; k0 += 8) {
        float4 av = *(const float4*)(Aptr + k0);
        float4 bv = *(const float4*)(Bptr + k0);
        __syncthreads();
        As[lc + 0][lr] = av.x; As[lc + 1][lr] = av.y;
        As[lc + 2][lr] = av.z; As[lc + 3][lr] = av.w;
        Bs[lc + 0][lr] = bv.x; Bs[lc + 1][lr] = bv.y;
        Bs[lc + 2][lr] = bv.z; Bs[lc + 3][lr] = bv.w;
        __syncthreads();
#pragma unroll
        for (int kk = 0; kk < 8; kk++) {
            float4 a0 = *(const float4*)&As[kk][tm];
            float4 a1 = *(const float4*)&As[kk][tm + 4];
            float4 b0 = *(const float4*)&Bs[kk][tn];
            float4 b1 = *(const float4*)&Bs[kk][tn + 4];
            float ra[8] = {a0.x, a0.y, a0.z, a0.w, a1.x, a1.y, a1.z, a1.w};
            float rb[8] = {b0.x, b0.y, b0.z, b0.w, b1.x, b1.y, b1.z, b1.w};
#pragma unroll
            for (int i = 0; i < 8; i++)
#pragma unroll
                for (int j = 0; j < 8; j++)
                    acc[i][j] = fmaf(ra[i], rb[j], acc[i][j]);
        }
    }

    // Epilogue
#pragma unroll
    for (int i = 0; i < 8; i++) {
        float* Crow = C + (size_t)(bm + tm + i) * N + bn + tn;
#pragma unroll
        for (int j = 0; j < 8; j += 4) {
            float4 o;
            float vals[4];
#pragma unroll
            for (int q = 0; q < 4; q++) {
                float x = acc[i][j + q];
                if (EPI == 2 || EPI == 3) x += bias[bn + tn + j + q];
                if (EPI == 1) x = (x > 0.f) ? (x + 1.f) : expf(x);   // elu(x)+1
                if (EPI == 2) {                                       // tanh-gelu (jax default)
                    float x3 = x * x * x;
                    x = 0.5f * x * (1.f + tanhf(0.7978845608028654f * (x + 0.044715f * x3)));
                }
                vals[q] = x;
            }
            o.x = vals[0]; o.y = vals[1]; o.z = vals[2]; o.w = vals[3];
            *(float4*)(Crow + j) = o;
        }
    }
}

// a[t,h] = sum_d kact[t, h*64+d]
__global__ void reduce_a_kernel()
{
    int idx = blockIdx.x * blockDim.x + threadIdx.x;   // t*NH + h
    if (idx >= SEQ * NH) return;
    int t = idx >> 4;
    int h = idx & 15;
    const float4* row = (const float4*)(g_kact + (size_t)t * NN + h * DH);
    float s = 0.f;
#pragma unroll
    for (int i = 0; i < 16; i++) {
        float4 r = row[i];
        s += r.x + r.y + r.z + r.w;
    }
    g_a[idx] = s;
}

// rden[t,h] = 1 / cumsum_t(a[.,h])   -- 16 independent sequences
__global__ void scan_den_kernel()
{
    int h = threadIdx.x;
    if (h >= NH) return;
    float acc = 0.f;
#pragma unroll 4
    for (int t = 0; t < SEQ; t++) {
        acc += g_a[t * NH + h];
        g_rden[t * NH + h] = 1.0f / acc;
    }
}

// attn[t, h*64+v] = cumsum_t(a*v) * rden  -- 1024 independent sequences
__global__ void scan_num_kernel()
{
    int idx = blockIdx.x * blockDim.x + threadIdx.x;   // h*DH + v, 1024 total
    int h = idx >> 6;
    float acc = 0.f;
#pragma unroll 4
    for (int t = 0; t < SEQ; t++) {
        float a  = g_a[t * NH + h];
        float vv = g_v[(size_t)t * NN + idx];
        acc = fmaf(a, vv, acc);
        g_attn[(size_t)t * NN + idx] = acc * g_rden[t * NH + h];
    }
}

extern "C" void kernel_launch(void* const* d_in, const int* in_sizes, int n_in,
                              void* d_out, int out_size)
{
    const float* xs = (const float*)d_in[0];
    // d_in[1] = wq: provably unused (query factor cancels in sq/zq)
    const float* wk = (const float*)d_in[2];
    const float* wv = (const float*)d_in[3];
    const float* w1 = (const float*)d_in[4];
    const float* b1 = (const float*)d_in[5];
    const float* w2 = (const float*)d_in[6];
    const float* b2 = (const float*)d_in[7];
    float* out = (float*)d_out;

    float *kact, *vbuf, *attn, *h1;
    cudaGetSymbolAddress((void**)&kact, g_kact);
    cudaGetSymbolAddress((void**)&vbuf, g_v);
    cudaGetSymbolAddress((void**)&attn, g_attn);
    cudaGetSymbolAddress((void**)&h1,   g_h1);

    dim3 grid(NN / 128, SEQ / 128);   // (8, 64)

    // k projection with fused act
    gemm_tn<1><<<grid, 256>>>(xs, wk, nullptr, kact, SEQ, NN, DM);
    // v projection
    gemm_tn<0><<<grid, 256>>>(xs, wv, nullptr, vbuf, SEQ, NN, DM);
    // per-(t,h) reduction of act(k)
    reduce_a_kernel<<<(SEQ * NH + 255) / 256, 256>>>();
    // denominator prefix (reciprocal)
    scan_den_kernel<<<1, 32>>>();
    // numerator prefix + normalize
    scan_num_kernel<<<16, 64>>>();
    // MLP
    gemm_tn<2><<<grid, 256>>>(attn, w1, b1, h1, SEQ, DM, NN);
    gemm_tn<3><<<grid, 256>>>(h1, w2, b2, out, SEQ, NN, DM);
}

// round 2
// speedup vs baseline: 1.1068x; 1.1068x over previous
#include <cuda_runtime.h>
#include <math.h>
#include <stdint.h>

#define SEQ 8192
#define DM 1024
#define NH 16
#define DH 64
#define NN (NH*DH)   // 1024

// Scratch (device globals; no allocation allowed in kernel_launch)
__device__ float g_kact[SEQ * NN];   // act(k) = elu(k)+1
__device__ float g_v[SEQ * NN];      // v projection
__device__ float g_a[SEQ * NH];      // a[t,h] = sum_d act(k[t,h,d])
__device__ float g_rden[SEQ * NH];   // 1 / cumsum(a)
__device__ float g_attn[SEQ * NN];   // attention output (pre-MLP)
__device__ float g_h1[SEQ * DM];     // gelu(attn @ w1^T + b1)

__device__ __forceinline__ uint32_t f2tf(float f) {
    uint32_t r;
    asm("cvt.rna.tf32.f32 %0, %1;" : "=r"(r) : "f"(f));
    return r;
}

// ---------------------------------------------------------------------------
// tf32 tensor-core GEMM: C[M,N] = A[M,K] @ B[N,K]^T   (row-major, B is [N,K])
// 128x128 CTA tile, K-panel 16, double buffered. 256 threads = 8 warps (2x4),
// each warp computes 64x32 via mma.sync.m16n8k8.tf32.
// Smem layout: [k][m] with XOR swizzle col = m ^ 8*((k&3)^(k>>2)) —
// conflict-free for both the store scatter and the fragment loads.
// EPI: 0=none, 1=elu(x)+1, 2=gelu(x+bias), 3=x+bias
// ---------------------------------------------------------------------------
template<int EPI>
__global__ __launch_bounds__(256)
void gemm_mma(const float* __restrict__ A, const float* __restrict__ B,
              const float* __restrict__ bias, float* __restrict__ C,
              int M, int N, int K)
{
    __shared__ uint32_t As[2][16][128];
    __shared__ uint32_t Bs[2][16][128];

    const int bm = blockIdx.y * 128;
    const int bn = blockIdx.x * 128;
    const int tid  = threadIdx.x;
    const int lane = tid & 31;
    const int wid  = tid >> 5;
    const int g    = lane >> 2;   // group id (0..7)
    const int tig  = lane & 3;    // thread in group

    const int warp_m = (wid >> 2) * 64;   // 0 or 64
    const int warp_n = (wid & 3) * 32;    // 0,32,64,96

    // global staging mapping: thread loads rows m0 and m0+64, k-quad kq
    const int m0 = tid >> 2;          // 0..63
    const int kq = (tid & 3) << 2;    // 0,4,8,12
    const int kq2 = kq >> 2;          // 0..3

    const float* pA0 = A + (size_t)(bm + m0) * K + kq;
    const float* pA1 = pA0 + (size_t)64 * K;
    const float* pB0 = B + (size_t)(bn + m0) * K + kq;
    const float* pB1 = pB0 + (size_t)64 * K;

    float acc[4][4][4];
#pragma unroll
    for (int i = 0; i < 4; i++)
#pragma unroll
        for (int j = 0; j < 4; j++)
#pragma unroll
            for (int q = 0; q < 4; q++) acc[i][j][q] = 0.f;

    const int nk = K / 16;   // 64 panels

    uint32_t va[2][4], vb[2][4];

    // ---- prologue: fetch + store panel 0 ----
    {
        float4 a0 = *(const float4*)pA0;
        float4 a1 = *(const float4*)pA1;
        float4 b0 = *(const float4*)pB0;
        float4 b1 = *(const float4*)pB1;
        va[0][0]=f2tf(a0.x); va[0][1]=f2tf(a0.y); va[0][2]=f2tf(a0.z); va[0][3]=f2tf(a0.w);
        va[1][0]=f2tf(a1.x); va[1][1]=f2tf(a1.y); va[1][2]=f2tf(a1.z); va[1][3]=f2tf(a1.w);
        vb[0][0]=f2tf(b0.x); vb[0][1]=f2tf(b0.y); vb[0][2]=f2tf(b0.z); vb[0][3]=f2tf(b0.w);
        vb[1][0]=f2tf(b1.x); vb[1][1]=f2tf(b1.y); vb[1][2]=f2tf(b1.z); vb[1][3]=f2tf(b1.w);
#pragma unroll
        for (int u = 0; u < 2; u++)
#pragma unroll
            for (int jj = 0; jj < 4; jj++) {
                int col = (m0 + 64*u) ^ (8 * (jj ^ kq2));
                As[0][kq + jj][col] = va[u][jj];
                Bs[0][kq + jj][col] = vb[u][jj];
            }
    }
    __syncthreads();

    for (int kt = 0; kt < nk; kt++) {
        const int buf = kt & 1;
        const bool more = (kt + 1 < nk);

        // issue next panel's global loads early
        float4 a0, a1, b0, b1;
        if (more) {
            size_t off = (size_t)(kt + 1) * 16;
            a0 = *(const float4*)(pA0 + off);
            a1 = *(const float4*)(pA1 + off);
            b0 = *(const float4*)(pB0 + off);
            b1 = *(const float4*)(pB1 + off);
        }

        // ---- compute current buffer: 2 k-steps of 8 ----
#pragma unroll
        for (int ks = 0; ks < 16; ks += 8) {
            const int ks4 = ks >> 2;            // 0 or 2
            const int s0 = 8 * (tig ^ ks4);
            const int s1 = 8 * (tig ^ (ks4 + 1));
            const int r0 = ks + tig;
            const int r1 = ks + tig + 4;

            uint32_t af[4][4], bf[4][2];
#pragma unroll
            for (int i = 0; i < 4; i++) {
                int mb = warp_m + 16*i + g;
                af[i][0] = As[buf][r0][ mb      ^ s0];
                af[i][1] = As[buf][r0][(mb + 8) ^ s0];
                af[i][2] = As[buf][r1][ mb      ^ s1];
                af[i][3] = As[buf][r1][(mb + 8) ^ s1];
            }
#pragma unroll
            for (int j = 0; j < 4; j++) {
                int nb = warp_n + 8*j + g;
                bf[j][0] = Bs[buf][r0][nb ^ s0];
                bf[j][1] = Bs[buf][r1][nb ^ s1];
            }
#pragma unroll
            for (int i = 0; i < 4; i++)
#pragma unroll
                for (int j = 0; j < 4; j++) {
                    asm volatile(
                        "mma.sync.aligned.m16n8k8.row.col.f32.tf32.tf32.f32 "
                        "{%0,%1,%2,%3}, {%4,%5,%6,%7}, {%8,%9}, {%0,%1,%2,%3};"
                        : "+f"(acc[i][j][0]), "+f"(acc[i][j][1]),
                          "+f"(acc[i][j][2]), "+f"(acc[i][j][3])
                        : "r"(af[i][0]), "r"(af[i][1]), "r"(af[i][2]), "r"(af[i][3]),
                          "r"(bf[j][0]), "r"(bf[j][1]));
                }
        }

        if (more) {
            va[0][0]=f2tf(a0.x); va[0][1]=f2tf(a0.y); va[0][2]=f2tf(a0.z); va[0][3]=f2tf(a0.w);
            va[1][0]=f2tf(a1.x); va[1][1]=f2tf(a1.y); va[1][2]=f2tf(a1.z); va[1][3]=f2tf(a1.w);
            vb[0][0]=f2tf(b0.x); vb[0][1]=f2tf(b0.y); vb[0][2]=f2tf(b0.z); vb[0][3]=f2tf(b0.w);
            vb[1][0]=f2tf(b1.x); vb[1][1]=f2tf(b1.y); vb[1][2]=f2tf(b1.z); vb[1][3]=f2tf(b1.w);
            const int nb = buf ^ 1;
#pragma unroll
            for (int u = 0; u < 2; u++)
#pragma unroll
                for (int jj = 0; jj < 4; jj++) {
                    int col = (m0 + 64*u) ^ (8 * (jj ^ kq2));
                    As[nb][kq + jj][col] = va[u][jj];
                    Bs[nb][kq + jj][col] = vb[u][jj];
                }
            __syncthreads();
        }
    }

    // ---- epilogue ----
#pragma unroll
    for (int i = 0; i < 4; i++) {
        int row0 = bm + warp_m + 16*i + g;
#pragma unroll
        for (int j = 0; j < 4; j++) {
            int colg = bn + warp_n + 8*j + 2*tig;
            float bia0 = 0.f, bia1 = 0.f;
            if (EPI == 2 || EPI == 3) { bia0 = bias[colg]; bia1 = bias[colg + 1]; }
#pragma unroll
            for (int half = 0; half < 2; half++) {
                int row = row0 + 8*half;
                float x0 = acc[i][j][2*half + 0];
                float x1 = acc[i][j][2*half + 1];
                if (EPI == 2 || EPI == 3) { x0 += bia0; x1 += bia1; }
                if (EPI == 1) {
                    x0 = (x0 > 0.f) ? (x0 + 1.f) : expf(x0);
                    x1 = (x1 > 0.f) ? (x1 + 1.f) : expf(x1);
                }
                if (EPI == 2) {
                    float t0 = 0.7978845608028654f * (x0 + 0.044715f * x0 * x0 * x0);
                    float t1 = 0.7978845608028654f * (x1 + 0.044715f * x1 * x1 * x1);
                    x0 = 0.5f * x0 * (1.f + tanhf(t0));
                    x1 = 0.5f * x1 * (1.f + tanhf(t1));
                }
                float2 o = make_float2(x0, x1);
                *(float2*)(C + (size_t)row * N + colg) = o;
            }
        }
    }
}

// a[t,h] = sum_d kact[t, h*64+d]
__global__ void reduce_a_kernel()
{
    int idx = blockIdx.x * blockDim.x + threadIdx.x;   // t*NH + h
    if (idx >= SEQ * NH) return;
    int t = idx >> 4;
    int h = idx & 15;
    const float4* row = (const float4*)(g_kact + (size_t)t * NN + h * DH);
    float s = 0.f;
#pragma unroll
    for (int i = 0; i < 16; i++) {
        float4 r = row[i];
        s += r.x + r.y + r.z + r.w;
    }
    g_a[idx] = s;
}

// rden[t,h] = 1 / cumsum_t(a[.,h])   -- 16 independent sequences
__global__ void scan_den_kernel()
{
    int h = threadIdx.x;
    if (h >= NH) return;
    float acc = 0.f;
#pragma unroll 4
    for (int t = 0; t < SEQ; t++) {
        acc += g_a[t * NH + h];
        g_rden[t * NH + h] = 1.0f / acc;
    }
}

// attn[t, h*64+v] = cumsum_t(a*v) * rden  -- 1024 independent sequences
__global__ void scan_num_kernel()
{
    int idx = blockIdx.x * blockDim.x + threadIdx.x;   // h*DH + v, 1024 total
    int h = idx >> 6;
    float acc = 0.f;
#pragma unroll 4
    for (int t = 0; t < SEQ; t++) {
        float a  = g_a[t * NH + h];
        float vv = g_v[(size_t)t * NN + idx];
        acc = fmaf(a, vv, acc);
        g_attn[(size_t)t * NN + idx] = acc * g_rden[t * NH + h];
    }
}

extern "C" void kernel_launch(void* const* d_in, const int* in_sizes, int n_in,
                              void* d_out, int out_size)
{
    const float* xs = (const float*)d_in[0];
    // d_in[1] = wq: provably unused (query factor cancels in sq/zq)
    const float* wk = (const float*)d_in[2];
    const float* wv = (const float*)d_in[3];
    const float* w1 = (const float*)d_in[4];
    const float* b1 = (const float*)d_in[5];
    const float* w2 = (const float*)d_in[6];
    const float* b2 = (const float*)d_in[7];
    float* out = (float*)d_out;

    float *kact, *vbuf, *attn, *h1;
    cudaGetSymbolAddress((void**)&kact, g_kact);
    cudaGetSymbolAddress((void**)&vbuf, g_v);
    cudaGetSymbolAddress((void**)&attn, g_attn);
    cudaGetSymbolAddress((void**)&h1,   g_h1);

    dim3 grid(NN / 128, SEQ / 128);   // (8, 64)

    // k projection with fused act
    gemm_mma<1><<<grid, 256>>>(xs, wk, nullptr, kact, SEQ, NN, DM);
    // v projection
    gemm_mma<0><<<grid, 256>>>(xs, wv, nullptr, vbuf, SEQ, NN, DM);
    // per-(t,h) reduction of act(k)
    reduce_a_kernel<<<(SEQ * NH + 255) / 256, 256>>>();
    // denominator prefix (reciprocal)
    scan_den_kernel<<<1, 32>>>();
    // numerator prefix + normalize
    scan_num_kernel<<<16, 64>>>();
    // MLP
    gemm_mma<2><<<grid, 256>>>(attn, w1, b1, h1, SEQ, DM, NN);
    gemm_mma<3><<<grid, 256>>>(h1, w2, b2, out, SEQ, NN, DM);
}

// round 4
// speedup vs baseline: 1.2366x; 1.1172x over previous
#include <cuda_runtime.h>
#include <math.h>
#include <stdint.h>

#define SEQ 8192
#define DM 1024
#define NH 16
#define DH 64
#define NN (NH*DH)   // 1024

#define KTOT 1024
#define KSTAGE 32
#define NSTG 3
#define NKT (KTOT/KSTAGE)          // 32 panels
#define STG_BYTES 32768            // A tile 16KB + B tile 16KB
#define SMEM_BYTES (NSTG*STG_BYTES)  // 98304

// ---------------- scratch ----------------
__device__ float g_xs_r[SEQ * DM];   // tf32-rounded inputs
__device__ float g_wk_r[NN * DM];
__device__ float g_wv_r[NN * DM];
__device__ float g_w1_r[DM * NN];
__device__ float g_w2_r[NN * DM];
__device__ float g_kact[SEQ * NN];   // act(k)
__device__ float g_v   [SEQ * NN];   // v projection
__device__ float g_a   [SEQ * NH];
__device__ float g_rden[SEQ * NH];
__device__ float g_attn[SEQ * NN];   // tf32-rounded at write
__device__ float g_h1  [SEQ * DM];   // tf32-rounded at write

__device__ __forceinline__ uint32_t f2tf(float f) {
    uint32_t r;
    asm("cvt.rna.tf32.f32 %0, %1;" : "=r"(r) : "f"(f));
    return r;
}
__device__ __forceinline__ uint32_t smem_u32(const void* p) {
    uint32_t a;
    asm("{ .reg .u64 t; cvta.to.shared.u64 t, %1; cvt.u32.u64 %0, t; }" : "=r"(a) : "l"(p));
    return a;
}

// issue one stage of cp.async loads (8 x 16B per thread) + commit
__device__ __forceinline__ void load_stage(uint32_t sb, int s, int kt,
                                           const float* gA, const float* gB,
                                           const uint32_t* doff)
{
    const uint32_t ab = sb + s * STG_BYTES;
    const uint32_t bb = ab + 16384;
    const float* a = gA + kt * KSTAGE;
    const float* b = gB + kt * KSTAGE;
#pragma unroll
    for (int i = 0; i < 4; i++) {
        asm volatile("cp.async.cg.shared.global [%0], [%1], 16;"
                     :: "r"(ab + doff[i]), "l"(a + i * 4) : "memory");
        asm volatile("cp.async.cg.shared.global [%0], [%1], 16;"
                     :: "r"(bb + doff[i]), "l"(b + i * 4) : "memory");
    }
    asm volatile("cp.async.commit_group;" ::: "memory");
}

// ---------------------------------------------------------------------------
// tf32 GEMM: C[8192,1024] = A[8192,1024] @ B[1024,1024]^T, inputs pre-rounded.
// 128x128 CTA, 8 warps (2x4) of 64x32, cp.async 3-stage, ldmatrix fragments.
// EPI: 0=none, 1=elu+1 (->g_kact), 2=gelu(x+b)+tf32 round, 3=x+b
// ---------------------------------------------------------------------------
template<int EPI>
__global__ __launch_bounds__(256, 2)
void gemm_lm(const float* __restrict__ A, const float* __restrict__ B,
             const float* __restrict__ bias, float* __restrict__ C)
{
    extern __shared__ float smf[];
    const uint32_t sb = smem_u32(smf);
    const int tid = threadIdx.x, lane = tid & 31, wid = tid >> 5;
    const int bm = blockIdx.y, bn = blockIdx.x;
    const int warp_m = (wid >> 2) * 64;
    const int warp_n = (wid & 3) * 32;

    // cp.async mapping: thread -> row (tid>>1), chunks cc0..cc0+3
    const int crow = tid >> 1;
    const int cc0 = (tid & 1) * 4;
    const float* gA = A + (size_t)(bm * 128 + crow) * KTOT + cc0 * 4;
    const float* gB = B + (size_t)(bn * 128 + crow) * KTOT + cc0 * 4;
    uint32_t doff[4];
#pragma unroll
    for (int i = 0; i < 4; i++)
        doff[i] = crow * 128 + (((cc0 + i) ^ (crow & 7)) << 4);

    // ldmatrix lane bases
    const int rA  = warp_m + ((lane >> 3) & 1) * 8 + (lane & 7);
    const int cA0 = lane >> 4;                 // 0..1
    const int rA7 = rA & 7;
    const int rB  = warp_n + (lane >> 4) * 8 + (lane & 7);
    const int cB0 = (lane >> 3) & 1;           // 0..1
    const int rB7 = rB & 7;

    float acc[4][4][4];
#pragma unroll
    for (int i = 0; i < 4; i++)
#pragma unroll
        for (int j = 0; j < 4; j++)
#pragma unroll
            for (int q = 0; q < 4; q++) acc[i][j][q] = 0.f;

    load_stage(sb, 0, 0, gA, gB, doff);
    load_stage(sb, 1, 1, gA, gB, doff);

    for (int kt = 0; kt < NKT; kt++) {
        if (kt + 1 < NKT) asm volatile("cp.async.wait_group 1;" ::: "memory");
        else              asm volatile("cp.async.wait_group 0;" ::: "memory");
        __syncthreads();
        if (kt + 2 < NKT) load_stage(sb, (kt + 2) % NSTG, kt + 2, gA, gB, doff);

        const uint32_t ab = sb + (kt % NSTG) * STG_BYTES;
        const uint32_t bb = ab + 16384;

#pragma unroll
        for (int kg = 0; kg < 4; kg++) {
            uint32_t bfr[8];
#pragma unroll
            for (int p = 0; p < 2; p++) {
                uint32_t addr = bb + (uint32_t)(rB + 16 * p) * 128
                              + (uint32_t)(((cB0 + 2 * kg) ^ rB7) << 4);
                asm volatile("ldmatrix.sync.aligned.m8n8.x4.shared.b16 {%0,%1,%2,%3}, [%4];"
                    : "=r"(bfr[4*p]), "=r"(bfr[4*p+1]), "=r"(bfr[4*p+2]), "=r"(bfr[4*p+3])
                    : "r"(addr));
            }
#pragma unroll
            for (int i = 0; i < 4; i++) {
                uint32_t af[4];
                uint32_t addr = ab + (uint32_t)rA * 128 + (uint32_t)(i * 2048)
                              + (uint32_t)(((cA0 + 2 * kg) ^ rA7) << 4);
                asm volatile("ldmatrix.sync.aligned.m8n8.x4.shared.b16 {%0,%1,%2,%3}, [%4];"
                    : "=r"(af[0]), "=r"(af[1]), "=r"(af[2]), "=r"(af[3]) : "r"(addr));
#pragma unroll
                for (int j = 0; j < 4; j++) {
                    const int bi = (j >> 1) * 4 + (j & 1) * 2;
                    asm volatile(
                        "mma.sync.aligned.m16n8k8.row.col.f32.tf32.tf32.f32 "
                        "{%0,%1,%2,%3}, {%4,%5,%6,%7}, {%8,%9}, {%0,%1,%2,%3};"
                        : "+f"(acc[i][j][0]), "+f"(acc[i][j][1]),
                          "+f"(acc[i][j][2]), "+f"(acc[i][j][3])
                        : "r"(af[0]), "r"(af[1]), "r"(af[2]), "r"(af[3]),
                          "r"(bfr[bi]), "r"(bfr[bi + 1]));
                }
            }
        }
    }

    // ---- epilogue (round-2 proven mapping) ----
    const int g = lane >> 2, tig = lane & 3;
#pragma unroll
    for (int i = 0; i < 4; i++) {
        int row0 = bm * 128 + warp_m + 16 * i + g;
#pragma unroll
        for (int j = 0; j < 4; j++) {
            int colg = bn * 128 + warp_n + 8 * j + 2 * tig;
            float bia0 = 0.f, bia1 = 0.f;
            if (EPI == 2 || EPI == 3) { bia0 = bias[colg]; bia1 = bias[colg + 1]; }
#pragma unroll
            for (int half = 0; half < 2; half++) {
                int row = row0 + 8 * half;
                float x0 = acc[i][j][2 * half + 0];
                float x1 = acc[i][j][2 * half + 1];
                if (EPI == 2 || EPI == 3) { x0 += bia0; x1 += bia1; }
                if (EPI == 1) {
                    x0 = (x0 > 0.f) ? (x0 + 1.f) : expf(x0);
                    x1 = (x1 > 0.f) ? (x1 + 1.f) : expf(x1);
                }
                if (EPI == 2) {
                    float t0 = 0.7978845608028654f * (x0 + 0.044715f * x0 * x0 * x0);
                    float t1 = 0.7978845608028654f * (x1 + 0.044715f * x1 * x1 * x1);
                    x0 = 0.5f * x0 * (1.f + tanhf(t0));
                    x1 = 0.5f * x1 * (1.f + tanhf(t1));
                    x0 = __uint_as_float(f2tf(x0));   // feeds next GEMM pre-rounded
                    x1 = __uint_as_float(f2tf(x1));
                }
                float2 o = make_float2(x0, x1);
                *(float2*)(C + (size_t)row * 1024 + colg) = o;
            }
        }
    }
}

// ---------------------------------------------------------------------------
__global__ void round_tf32(const float* __restrict__ src, float* __restrict__ dst, int n4)
{
    int i = blockIdx.x * blockDim.x + threadIdx.x;
    if (i >= n4) return;
    float4 v = ((const float4*)src)[i];
    uint4 o;
    o.x = f2tf(v.x); o.y = f2tf(v.y); o.z = f2tf(v.z); o.w = f2tf(v.w);
    ((uint4*)dst)[i] = o;
}

// a[t,h] = sum_d kact[t, h*64+d]
__global__ void reduce_a_kernel()
{
    int idx = blockIdx.x * blockDim.x + threadIdx.x;
    if (idx >= SEQ * NH) return;
    int t = idx >> 4;
    int h = idx & 15;
    const float4* row = (const float4*)(g_kact + (size_t)t * NN + h * DH);
    float s = 0.f;
#pragma unroll
    for (int i = 0; i < 16; i++) {
        float4 r = row[i];
        s += r.x + r.y + r.z + r.w;
    }
    g_a[idx] = s;
}

__global__ void scan_den_kernel()
{
    int h = threadIdx.x;
    if (h >= NH) return;
    float acc = 0.f;
#pragma unroll 4
    for (int t = 0; t < SEQ; t++) {
        acc += g_a[t * NH + h];
        g_rden[t * NH + h] = 1.0f / acc;
    }
}

__global__ void scan_num_kernel()
{
    int idx = blockIdx.x * blockDim.x + threadIdx.x;
    int h = idx >> 6;
    float acc = 0.f;
#pragma unroll 4
    for (int t = 0; t < SEQ; t++) {
        float a  = g_a[t * NH + h];
        float vv = g_v[(size_t)t * NN + idx];
        acc = fmaf(a, vv, acc);
        float val = acc * g_rden[t * NH + h];
        g_attn[(size_t)t * NN + idx] = __uint_as_float(f2tf(val));  // pre-rounded for MLP1
    }
}

// ---------------------------------------------------------------------------
extern "C" void kernel_launch(void* const* d_in, const int* in_sizes, int n_in,
                              void* d_out, int out_size)
{
    const float* xs = (const float*)d_in[0];
    // d_in[1] = wq: unused (query factor cancels in sq/zq)
    const float* wk = (const float*)d_in[2];
    const float* wv = (const float*)d_in[3];
    const float* w1 = (const float*)d_in[4];
    const float* b1 = (const float*)d_in[5];
    const float* w2 = (const float*)d_in[6];
    const float* b2 = (const float*)d_in[7];
    float* out = (float*)d_out;

    float *xs_r, *wk_r, *wv_r, *w1_r, *w2_r, *kact, *vbuf, *attn, *h1;
    cudaGetSymbolAddress((void**)&xs_r, g_xs_r);
    cudaGetSymbolAddress((void**)&wk_r, g_wk_r);
    cudaGetSymbolAddress((void**)&wv_r, g_wv_r);
    cudaGetSymbolAddress((void**)&w1_r, g_w1_r);
    cudaGetSymbolAddress((void**)&w2_r, g_w2_r);
    cudaGetSymbolAddress((void**)&kact, g_kact);
    cudaGetSymbolAddress((void**)&vbuf, g_v);
    cudaGetSymbolAddress((void**)&attn, g_attn);
    cudaGetSymbolAddress((void**)&h1,   g_h1);

    cudaFuncSetAttribute(gemm_lm<0>, cudaFuncAttributeMaxDynamicSharedMemorySize, SMEM_BYTES);
    cudaFuncSetAttribute(gemm_lm<1>, cudaFuncAttributeMaxDynamicSharedMemorySize, SMEM_BYTES);
    cudaFuncSetAttribute(gemm_lm<2>, cudaFuncAttributeMaxDynamicSharedMemorySize, SMEM_BYTES);
    cudaFuncSetAttribute(gemm_lm<3>, cudaFuncAttributeMaxDynamicSharedMemorySize, SMEM_BYTES);

    // pre-round all GEMM inputs to tf32 (hoists cvt out of hot loops)
    round_tf32<<<(SEQ * DM / 4 + 255) / 256, 256>>>(xs, xs_r, SEQ * DM / 4);
    round_tf32<<<(NN * DM / 4 + 255) / 256, 256>>>(wk, wk_r, NN * DM / 4);
    round_tf32<<<(NN * DM / 4 + 255) / 256, 256>>>(wv, wv_r, NN * DM / 4);
    round_tf32<<<(DM * NN / 4 + 255) / 256, 256>>>(w1, w1_r, DM * NN / 4);
    round_tf32<<<(NN * DM / 4 + 255) / 256, 256>>>(w2, w2_r, NN * DM / 4);

    dim3 grid(NN / 128, SEQ / 128);   // (8, 64)

    gemm_lm<1><<<grid, 256, SMEM_BYTES>>>(xs_r, wk_r, nullptr, kact);
    gemm_lm<0><<<grid, 256, SMEM_BYTES>>>(xs_r, wv_r, nullptr, vbuf);

    reduce_a_kernel<<<(SEQ * NH + 255) / 256, 256>>>();
    scan_den_kernel<<<1, 32>>>();
    scan_num_kernel<<<16, 64>>>();

    gemm_lm<2><<<grid, 256, SMEM_BYTES>>>(attn, w1_r, b1, h1);
    gemm_lm<3><<<grid, 256, SMEM_BYTES>>>(h1, w2_r, b2, out);
}

// round 5
// speedup vs baseline: 15.7871x; 12.7670x over previous
#include <cuda_runtime.h>
#include <cuda_fp16.h>
#include <math.h>
#include <stdint.h>

#define SEQ 8192
#define DM 1024
#define NH 16
#define DH 64
#define NN (NH*DH)   // 1024

#define KTOT 1024
#define KSTAGE 64                  // halves per panel row (128B)
#define NSTG 3
#define NKT (KTOT/KSTAGE)          // 16 panels
#define STG_BYTES 32768            // A tile 16KB + B tile 16KB
#define SMEM_BYTES (NSTG*STG_BYTES)  // 98304

// ---------------- scratch ----------------
__device__ __half g_xs_h[SEQ * DM];
__device__ __half g_wk_h[NN * DM];
__device__ __half g_wv_h[NN * DM];
__device__ __half g_w1_h[DM * NN];
__device__ __half g_w2_h[NN * DM];
__device__ __half g_attn_h[SEQ * NN];
__device__ __half g_h1_h[SEQ * DM];
__device__ float g_kact[SEQ * NN];
__device__ float g_v   [SEQ * NN];
__device__ float g_a   [SEQ * NH];
__device__ float g_pav [64 * NN];
__device__ float g_bav [64 * NN];
__device__ float g_basea[64 * NH];

__device__ __forceinline__ uint32_t smem_u32(const void* p) {
    uint32_t a;
    asm("{ .reg .u64 t; cvta.to.shared.u64 t, %1; cvt.u32.u64 %0, t; }" : "=r"(a) : "l"(p));
    return a;
}

// one stage: 8 x 16B cp.async per thread
__device__ __forceinline__ void load_stage(uint32_t sb, int s, int kt,
                                           const __half* gA, const __half* gB,
                                           const uint32_t* doff)
{
    const uint32_t ab = sb + s * STG_BYTES;
    const uint32_t bb = ab + 16384;
    const __half* a = gA + kt * KSTAGE;
    const __half* b = gB + kt * KSTAGE;
#pragma unroll
    for (int i = 0; i < 4; i++) {
        asm volatile("cp.async.cg.shared.global [%0], [%1], 16;"
                     :: "r"(ab + doff[i]), "l"(a + i * 8) : "memory");
        asm volatile("cp.async.cg.shared.global [%0], [%1], 16;"
                     :: "r"(bb + doff[i]), "l"(b + i * 8) : "memory");
    }
    asm volatile("cp.async.commit_group;" ::: "memory");
}

// ---------------------------------------------------------------------------
// fp16 GEMM: C[8192,1024] = A[8192,1024] @ B[1024,1024]^T, f32 accumulate.
// 128x128 CTA, 8 warps (2x4) of 64x32, cp.async 3-stage, ldmatrix, m16n8k16.
// EPI: 0=none->f32, 1=elu+1->f32(g_kact), 2=gelu(x+b)->fp16(g_h1_h), 3=x+b->f32
// ---------------------------------------------------------------------------
template<int EPI>
__global__ __launch_bounds__(256, 2)
void gemm_h(const __half* __restrict__ A, const __half* __restrict__ B,
            const float* __restrict__ bias, void* __restrict__ Cv)
{
    extern __shared__ float smf[];
    const uint32_t sb = smem_u32(smf);
    const int tid = threadIdx.x, lane = tid & 31, wid = tid >> 5;
    const int bm = blockIdx.y, bn = blockIdx.x;
    const int warp_m = (wid >> 2) * 64;
    const int warp_n = (wid & 3) * 32;

    // cp.async mapping: thread -> row (tid>>1), 16B chunks cc0..cc0+3 (8 per row)
    const int crow = tid >> 1;
    const int cc0 = (tid & 1) * 4;
    const __half* gA = A + (size_t)(bm * 128 + crow) * KTOT + cc0 * 8;
    const __half* gB = B + (size_t)(bn * 128 + crow) * KTOT + cc0 * 8;
    uint32_t doff[4];
#pragma unroll
    for (int i = 0; i < 4; i++)
        doff[i] = crow * 128 + (((cc0 + i) ^ (crow & 7)) << 4);

    // ldmatrix lane bases (x4: lanes0-7 mat0, 8-15 mat1, 16-23 mat2, 24-31 mat3)
    const int rbase = (lane & 7) + ((lane >> 3) & 1) * 8;  // row within 16-block
    const int klane = lane >> 4;                           // 0/1 -> k chunk select
    const int rA_base = warp_m + rbase;
    const int rB_base = warp_n + rbase;

    float acc[4][4][4];
#pragma unroll
    for (int i = 0; i < 4; i++)
#pragma unroll
        for (int j = 0; j < 4; j++)
#pragma unroll
            for (int q = 0; q < 4; q++) acc[i][j][q] = 0.f;

    load_stage(sb, 0, 0, gA, gB, doff);
    load_stage(sb, 1, 1, gA, gB, doff);

    for (int kt = 0; kt < NKT; kt++) {
        if (kt + 1 < NKT) asm volatile("cp.async.wait_group 1;" ::: "memory");
        else              asm volatile("cp.async.wait_group 0;" ::: "memory");
        __syncthreads();
        if (kt + 2 < NKT) load_stage(sb, (kt + 2) % NSTG, kt + 2, gA, gB, doff);

        const uint32_t ab = sb + (kt % NSTG) * STG_BYTES;
        const uint32_t bb = ab + 16384;

#pragma unroll
        for (int kg = 0; kg < 4; kg++) {
            const int kc = 2 * kg + klane;
            uint32_t bfr[8];
#pragma unroll
            for (int p = 0; p < 2; p++) {
                const int row = rB_base + 16 * p;
                uint32_t addr = bb + (uint32_t)row * 128 + (uint32_t)((kc ^ (row & 7)) << 4);
                asm volatile("ldmatrix.sync.aligned.m8n8.x4.shared.b16 {%0,%1,%2,%3}, [%4];"
                    : "=r"(bfr[4*p]), "=r"(bfr[4*p+1]), "=r"(bfr[4*p+2]), "=r"(bfr[4*p+3])
                    : "r"(addr));
            }
#pragma unroll
            for (int i = 0; i < 4; i++) {
                const int row = rA_base + 16 * i;
                uint32_t af[4];
                uint32_t addr = ab + (uint32_t)row * 128 + (uint32_t)((kc ^ (row & 7)) << 4);
                asm volatile("ldmatrix.sync.aligned.m8n8.x4.shared.b16 {%0,%1,%2,%3}, [%4];"
                    : "=r"(af[0]), "=r"(af[1]), "=r"(af[2]), "=r"(af[3]) : "r"(addr));
#pragma unroll
                for (int j = 0; j < 4; j++) {
                    const int bi = (j >> 1) * 4 + (j & 1);
                    asm volatile(
                        "mma.sync.aligned.m16n8k16.row.col.f32.f16.f16.f32 "
                        "{%0,%1,%2,%3}, {%4,%5,%6,%7}, {%8,%9}, {%0,%1,%2,%3};"
                        : "+f"(acc[i][j][0]), "+f"(acc[i][j][1]),
                          "+f"(acc[i][j][2]), "+f"(acc[i][j][3])
                        : "r"(af[0]), "r"(af[1]), "r"(af[2]), "r"(af[3]),
                          "r"(bfr[bi]), "r"(bfr[bi + 2]));
                }
            }
        }
    }

    // ---- epilogue ----
    const int g = lane >> 2, tig = lane & 3;
#pragma unroll
    for (int i = 0; i < 4; i++) {
        int row0 = bm * 128 + warp_m + 16 * i + g;
#pragma unroll
        for (int j = 0; j < 4; j++) {
            int colg = bn * 128 + warp_n + 8 * j + 2 * tig;
            float bia0 = 0.f, bia1 = 0.f;
            if (EPI == 2 || EPI == 3) { bia0 = bias[colg]; bia1 = bias[colg + 1]; }
#pragma unroll
            for (int half = 0; half < 2; half++) {
                int row = row0 + 8 * half;
                float x0 = acc[i][j][2 * half + 0];
                float x1 = acc[i][j][2 * half + 1];
                if (EPI == 2 || EPI == 3) { x0 += bia0; x1 += bia1; }
                if (EPI == 1) {
                    x0 = (x0 > 0.f) ? (x0 + 1.f) : expf(x0);
                    x1 = (x1 > 0.f) ? (x1 + 1.f) : expf(x1);
                }
                if (EPI == 2) {
                    float t0 = 0.7978845608028654f * (x0 + 0.044715f * x0 * x0 * x0);
                    float t1 = 0.7978845608028654f * (x1 + 0.044715f * x1 * x1 * x1);
                    x0 = 0.5f * x0 * (1.f + tanhf(t0));
                    x1 = 0.5f * x1 * (1.f + tanhf(t1));
                    __half2 o = __halves2half2(__float2half_rn(x0), __float2half_rn(x1));
                    *(__half2*)((__half*)Cv + (size_t)row * 1024 + colg) = o;
                } else {
                    float2 o = make_float2(x0, x1);
                    *(float2*)((float*)Cv + (size_t)row * 1024 + colg) = o;
                }
            }
        }
    }
}

// ---------------------------------------------------------------------------
__global__ void conv_h(const float* __restrict__ src, __half* __restrict__ dst, int n4)
{
    int i = blockIdx.x * blockDim.x + threadIdx.x;
    if (i >= n4) return;
    float4 v = ((const float4*)src)[i];
    __half2 lo = __halves2half2(__float2half_rn(v.x), __float2half_rn(v.y));
    __half2 hi = __halves2half2(__float2half_rn(v.z), __float2half_rn(v.w));
    ((__half2*)dst)[2 * i]     = lo;
    ((__half2*)dst)[2 * i + 1] = hi;
}

__global__ void conv_h2(const float* __restrict__ sa, __half* __restrict__ da, int n4a,
                        const float* __restrict__ sb, __half* __restrict__ db, int n4b)
{
    int i = blockIdx.x * blockDim.x + threadIdx.x;
    const float* s; __half* d;
    if (i < n4a) { s = sa; d = da; }
    else if (i < n4a + n4b) { s = sb; d = db; i -= n4a; }
    else return;
    float4 v = ((const float4*)s)[i];
    __half2 lo = __halves2half2(__float2half_rn(v.x), __float2half_rn(v.y));
    __half2 hi = __halves2half2(__float2half_rn(v.z), __float2half_rn(v.w));
    ((__half2*)d)[2 * i]     = lo;
    ((__half2*)d)[2 * i + 1] = hi;
}

// a[t,h] = sum_d kact[t, h*64+d]
__global__ void reduce_a_kernel()
{
    int idx = blockIdx.x * blockDim.x + threadIdx.x;
    if (idx >= SEQ * NH) return;
    int t = idx >> 4;
    int h = idx & 15;
    const float4* row = (const float4*)(g_kact + (size_t)t * NN + h * DH);
    float s = 0.f;
#pragma unroll
    for (int i = 0; i < 16; i++) {
        float4 r = row[i];
        s += r.x + r.y + r.z + r.w;
    }
    g_a[idx] = s;
}

// ---- chunked scans: 64 chunks of 128 steps ----
// pass1: per-chunk sums of a*v
__global__ void scan_pass1()
{
    const int c = blockIdx.x, h = blockIdx.y, v = threadIdx.x;
    __shared__ float a_s[128];
    a_s[v]      = g_a[(c * 128 + v) * NH + h];
    a_s[v + 64] = g_a[(c * 128 + v + 64) * NH + h];
    __syncthreads();
    const int hv = h * DH + v;
    float acc = 0.f;
#pragma unroll 4
    for (int t = 0; t < 128; t++)
        acc = fmaf(a_s[t], g_v[(size_t)(c * 128 + t) * NN + hv], acc);
    g_pav[c * NN + hv] = acc;
}

// pass2a: chunk sums of a + exclusive scan
__global__ void scan_pass2a()
{
    __shared__ float pa[64 * NH];
    const int tid = threadIdx.x;
    const int c = tid >> 4, h = tid & 15;
    float s = 0.f;
    for (int i = 0; i < 128; i++) s += g_a[(c * 128 + i) * NH + h];
    pa[c * NH + h] = s;
    __syncthreads();
    if (tid < NH) {
        float acc = 0.f;
        for (int cc = 0; cc < 64; cc++) {
            float x = pa[cc * NH + tid];
            g_basea[cc * NH + tid] = acc;
            acc += x;
        }
    }
}

// pass2c: exclusive scan of pav over chunks
__global__ void scan_pass2c()
{
    const int hv = blockIdx.x * blockDim.x + threadIdx.x;
    float acc = 0.f;
    for (int c = 0; c < 64; c++) {
        float x = g_pav[c * NN + hv];
        g_bav[c * NN + hv] = acc;
        acc += x;
    }
}

// pass3: within-chunk scan + normalize -> fp16 attn
__global__ void scan_pass3()
{
    const int c = blockIdx.x, h = blockIdx.y, v = threadIdx.x;
    __shared__ float a_s[128];
    __shared__ float inv_s[128];
    a_s[v]      = g_a[(c * 128 + v) * NH + h];
    a_s[v + 64] = g_a[(c * 128 + v + 64) * NH + h];
    __syncthreads();
    if (v == 0) {
        float run = g_basea[c * NH + h];
        for (int t = 0; t < 128; t++) { run += a_s[t]; inv_s[t] = run; }
    }
    __syncthreads();
    inv_s[v]      = 1.0f / inv_s[v];
    inv_s[v + 64] = 1.0f / inv_s[v + 64];
    __syncthreads();

    const int hv = h * DH + v;
    float acc = g_bav[c * NN + hv];
#pragma unroll 4
    for (int t = 0; t < 128; t++) {
        acc = fmaf(a_s[t], g_v[(size_t)(c * 128 + t) * NN + hv], acc);
        g_attn_h[(size_t)(c * 128 + t) * NN + hv] = __float2half_rn(acc * inv_s[t]);
    }
}

// ---------------------------------------------------------------------------
extern "C" void kernel_launch(void* const* d_in, const int* in_sizes, int n_in,
                              void* d_out, int out_size)
{
    const float* xs = (const float*)d_in[0];
    // d_in[1] = wq: unused (query factor cancels in sq/zq)
    const float* wk = (const float*)d_in[2];
    const float* wv = (const float*)d_in[3];
    const float* w1 = (const float*)d_in[4];
    const float* b1 = (const float*)d_in[5];
    const float* w2 = (const float*)d_in[6];
    const float* b2 = (const float*)d_in[7];
    float* out = (float*)d_out;

    __half *xs_h, *wk_h, *wv_h, *w1_h, *w2_h, *attn_h, *h1_h;
    float *kact, *vbuf;
    cudaGetSymbolAddress((void**)&xs_h, g_xs_h);
    cudaGetSymbolAddress((void**)&wk_h, g_wk_h);
    cudaGetSymbolAddress((void**)&wv_h, g_wv_h);
    cudaGetSymbolAddress((void**)&w1_h, g_w1_h);
    cudaGetSymbolAddress((void**)&w2_h, g_w2_h);
    cudaGetSymbolAddress((void**)&attn_h, g_attn_h);
    cudaGetSymbolAddress((void**)&h1_h, g_h1_h);
    cudaGetSymbolAddress((void**)&kact, g_kact);
    cudaGetSymbolAddress((void**)&vbuf, g_v);

    cudaFuncSetAttribute(gemm_h<0>, cudaFuncAttributeMaxDynamicSharedMemorySize, SMEM_BYTES);
    cudaFuncSetAttribute(gemm_h<1>, cudaFuncAttributeMaxDynamicSharedMemorySize, SMEM_BYTES);
    cudaFuncSetAttribute(gemm_h<2>, cudaFuncAttributeMaxDynamicSharedMemorySize, SMEM_BYTES);
    cudaFuncSetAttribute(gemm_h<3>, cudaFuncAttributeMaxDynamicSharedMemorySize, SMEM_BYTES);

    // conversions (4 launches so the projection GEMMs land at launches 5-6 for ncu)
    conv_h<<<(SEQ * DM / 4 + 255) / 256, 256>>>(xs, xs_h, SEQ * DM / 4);
    conv_h<<<(NN * DM / 4 + 255) / 256, 256>>>(wk, wk_h, NN * DM / 4);
    conv_h<<<(NN * DM / 4 + 255) / 256, 256>>>(wv, wv_h, NN * DM / 4);
    conv_h2<<<(2 * NN * DM / 4 + 255) / 256, 256>>>(w1, w1_h, DM * NN / 4, w2, w2_h, NN * DM / 4);

    dim3 grid(NN / 128, SEQ / 128);   // (8, 64)

    gemm_h<1><<<grid, 256, SMEM_BYTES>>>(xs_h, wk_h, nullptr, kact);
    gemm_h<0><<<grid, 256, SMEM_BYTES>>>(xs_h, wv_h, nullptr, vbuf);

    reduce_a_kernel<<<(SEQ * NH + 255) / 256, 256>>>();
    scan_pass1<<<dim3(64, NH), DH>>>();
    scan_pass2a<<<1, 1024>>>();
    scan_pass2c<<<4, 256>>>();
    scan_pass3<<<dim3(64, NH), DH>>>();

    gemm_h<2><<<grid, 256, SMEM_BYTES>>>(attn_h, w1_h, b1, h1_h);
    gemm_h<3><<<grid, 256, SMEM_BYTES>>>(h1_h, w2_h, b2, out);
}

// round 6
// speedup vs baseline: 16.5433x; 1.0479x over previous
#include <cuda_runtime.h>
#include <cuda_fp16.h>
#include <math.h>
#include <stdint.h>

#define SEQ 8192
#define DM 1024
#define NH 16
#define DH 64
#define NN (NH*DH)   // 1024

#define KTOT 1024
#define KSTAGE 64                  // halves per panel row (128B)
#define NSTG 3
#define NKT (KTOT/KSTAGE)          // 16 panels
#define STG_BYTES 32768            // A tile 16KB + B tile 16KB
#define SMEM_BYTES (NSTG*STG_BYTES)  // 98304

// ---------------- scratch ----------------
__device__ __half g_xs_h[SEQ * DM];
__device__ __half g_wk_h[NN * DM];
__device__ __half g_wv_h[NN * DM];
__device__ __half g_w1_h[DM * NN];
__device__ __half g_w2_h[NN * DM];
__device__ __half g_attn_h[SEQ * NN];
__device__ __half g_h1_h[SEQ * DM];
__device__ __half g_v_h[SEQ * NN];   // v projection, fp16
__device__ float g_a   [SEQ * NH];
__device__ float g_pav [64 * NN];
__device__ float g_bav [64 * NN];
__device__ float g_basea[64 * NH];

__device__ __forceinline__ uint32_t smem_u32(const void* p) {
    uint32_t a;
    asm("{ .reg .u64 t; cvta.to.shared.u64 t, %1; cvt.u32.u64 %0, t; }" : "=r"(a) : "l"(p));
    return a;
}

// one stage: 8 x 16B cp.async per thread
__device__ __forceinline__ void load_stage(uint32_t sb, int s, int kt,
                                           const __half* gA, const __half* gB,
                                           const uint32_t* doff)
{
    const uint32_t ab = sb + s * STG_BYTES;
    const uint32_t bb = ab + 16384;
    const __half* a = gA + kt * KSTAGE;
    const __half* b = gB + kt * KSTAGE;
#pragma unroll
    for (int i = 0; i < 4; i++) {
        asm volatile("cp.async.cg.shared.global [%0], [%1], 16;"
                     :: "r"(ab + doff[i]), "l"(a + i * 8) : "memory");
        asm volatile("cp.async.cg.shared.global [%0], [%1], 16;"
                     :: "r"(bb + doff[i]), "l"(b + i * 8) : "memory");
    }
    asm volatile("cp.async.commit_group;" ::: "memory");
}

// ---------------------------------------------------------------------------
// fp16 GEMM: C[8192,1024] = A[8192,1024] @ B[1024,1024]^T, f32 accumulate.
// 128x128 CTA, 8 warps (2x4) of 64x32, cp.async 3-stage, ldmatrix, m16n8k16.
// EPI: 0 = ->fp16 (g_v_h)
//      1 = elu+1, fused per-head 64-col reduction -> g_a [SEQ x NH]
//      2 = gelu(x+b) -> fp16 (g_h1_h)
//      3 = x+b -> f32 (out)
// ---------------------------------------------------------------------------
template<int EPI>
__global__ __launch_bounds__(256, 2)
void gemm_h(const __half* __restrict__ A, const __half* __restrict__ B,
            const float* __restrict__ bias, void* __restrict__ Cv)
{
    extern __shared__ float smf[];
    const uint32_t sb = smem_u32(smf);
    const int tid = threadIdx.x, lane = tid & 31, wid = tid >> 5;
    const int bm = blockIdx.y, bn = blockIdx.x;
    const int warp_m = (wid >> 2) * 64;
    const int warp_n = (wid & 3) * 32;

    // cp.async mapping: thread -> row (tid>>1), 16B chunks cc0..cc0+3 (8 per row)
    const int crow = tid >> 1;
    const int cc0 = (tid & 1) * 4;
    const __half* gA = A + (size_t)(bm * 128 + crow) * KTOT + cc0 * 8;
    const __half* gB = B + (size_t)(bn * 128 + crow) * KTOT + cc0 * 8;
    uint32_t doff[4];
#pragma unroll
    for (int i = 0; i < 4; i++)
        doff[i] = crow * 128 + (((cc0 + i) ^ (crow & 7)) << 4);

    // ldmatrix lane bases
    const int rbase = (lane & 7) + ((lane >> 3) & 1) * 8;
    const int klane = lane >> 4;
    const int rA_base = warp_m + rbase;
    const int rB_base = warp_n + rbase;

    float acc[4][4][4];
#pragma unroll
    for (int i = 0; i < 4; i++)
#pragma unroll
        for (int j = 0; j < 4; j++)
#pragma unroll
            for (int q = 0; q < 4; q++) acc[i][j][q] = 0.f;

    load_stage(sb, 0, 0, gA, gB, doff);
    load_stage(sb, 1, 1, gA, gB, doff);

    for (int kt = 0; kt < NKT; kt++) {
        if (kt + 1 < NKT) asm volatile("cp.async.wait_group 1;" ::: "memory");
        else              asm volatile("cp.async.wait_group 0;" ::: "memory");
        __syncthreads();
        if (kt + 2 < NKT) load_stage(sb, (kt + 2) % NSTG, kt + 2, gA, gB, doff);

        const uint32_t ab = sb + (kt % NSTG) * STG_BYTES;
        const uint32_t bb = ab + 16384;

#pragma unroll
        for (int kg = 0; kg < 4; kg++) {
            const int kc = 2 * kg + klane;
            uint32_t bfr[8];
#pragma unroll
            for (int p = 0; p < 2; p++) {
                const int row = rB_base + 16 * p;
                uint32_t addr = bb + (uint32_t)row * 128 + (uint32_t)((kc ^ (row & 7)) << 4);
                asm volatile("ldmatrix.sync.aligned.m8n8.x4.shared.b16 {%0,%1,%2,%3}, [%4];"
                    : "=r"(bfr[4*p]), "=r"(bfr[4*p+1]), "=r"(bfr[4*p+2]), "=r"(bfr[4*p+3])
                    : "r"(addr));
            }
#pragma unroll
            for (int i = 0; i < 4; i++) {
                const int row = rA_base + 16 * i;
                uint32_t af[4];
                uint32_t addr = ab + (uint32_t)row * 128 + (uint32_t)((kc ^ (row & 7)) << 4);
                asm volatile("ldmatrix.sync.aligned.m8n8.x4.shared.b16 {%0,%1,%2,%3}, [%4];"
                    : "=r"(af[0]), "=r"(af[1]), "=r"(af[2]), "=r"(af[3]) : "r"(addr));
#pragma unroll
                for (int j = 0; j < 4; j++) {
                    const int bi = (j >> 1) * 4 + (j & 1);
                    asm volatile(
                        "mma.sync.aligned.m16n8k16.row.col.f32.f16.f16.f32 "
                        "{%0,%1,%2,%3}, {%4,%5,%6,%7}, {%8,%9}, {%0,%1,%2,%3};"
                        : "+f"(acc[i][j][0]), "+f"(acc[i][j][1]),
                          "+f"(acc[i][j][2]), "+f"(acc[i][j][3])
                        : "r"(af[0]), "r"(af[1]), "r"(af[2]), "r"(af[3]),
                          "r"(bfr[bi]), "r"(bfr[bi + 2]));
                }
            }
        }
    }

    const int g = lane >> 2, tig = lane & 3;

    if (EPI == 1) {
        // fused act + per-head reduction: sum elu(x)+1 over the 64 cols of each head.
        // red[] lives in stage-1 smem (last panel kt=15 reads stage 0 only -> safe).
        float* red = smf + 8192;   // [128 rows][4 warp_n groups]
#pragma unroll
        for (int i = 0; i < 4; i++) {
#pragma unroll
            for (int half = 0; half < 2; half++) {
                float s = 0.f;
#pragma unroll
                for (int j = 0; j < 4; j++) {
                    float x0 = acc[i][j][2 * half + 0];
                    float x1 = acc[i][j][2 * half + 1];
                    s += (x0 > 0.f) ? (x0 + 1.f) : expf(x0);
                    s += (x1 > 0.f) ? (x1 + 1.f) : expf(x1);
                }
                s += __shfl_xor_sync(0xFFFFFFFFu, s, 1);
                s += __shfl_xor_sync(0xFFFFFFFFu, s, 2);
                if (tig == 0)
                    red[(warp_m + 16 * i + 8 * half + g) * 4 + (wid & 3)] = s;
            }
        }
        __syncthreads();
        {
            const int row = tid >> 1, hsel = tid & 1;
            float s = red[row * 4 + 2 * hsel] + red[row * 4 + 2 * hsel + 1];
            g_a[(size_t)(bm * 128 + row) * NH + bn * 2 + hsel] = s;
        }
        return;
    }

#pragma unroll
    for (int i = 0; i < 4; i++) {
        int row0 = bm * 128 + warp_m + 16 * i + g;
#pragma unroll
        for (int j = 0; j < 4; j++) {
            int colg = bn * 128 + warp_n + 8 * j + 2 * tig;
            float bia0 = 0.f, bia1 = 0.f;
            if (EPI == 2 || EPI == 3) { bia0 = bias[colg]; bia1 = bias[colg + 1]; }
#pragma unroll
            for (int half = 0; half < 2; half++) {
                int row = row0 + 8 * half;
                float x0 = acc[i][j][2 * half + 0];
                float x1 = acc[i][j][2 * half + 1];
                if (EPI == 2 || EPI == 3) { x0 += bia0; x1 += bia1; }
                if (EPI == 2) {
                    float t0 = 0.7978845608028654f * (x0 + 0.044715f * x0 * x0 * x0);
                    float t1 = 0.7978845608028654f * (x1 + 0.044715f * x1 * x1 * x1);
                    x0 = 0.5f * x0 * (1.f + tanhf(t0));
                    x1 = 0.5f * x1 * (1.f + tanhf(t1));
                }
                if (EPI == 0 || EPI == 2) {
                    __half2 o = __floats2half2_rn(x0, x1);
                    *(__half2*)((__half*)Cv + (size_t)row * 1024 + colg) = o;
                } else {
                    float2 o = make_float2(x0, x1);
                    *(float2*)((float*)Cv + (size_t)row * 1024 + colg) = o;
                }
            }
        }
    }
}

// ---------------------------------------------------------------------------
// f32 -> fp16 conversion, ILP=4 grid-stride
__global__ void conv_xs(const float4* __restrict__ src, __half2* __restrict__ dst, int n4)
{
    const int stride = gridDim.x * blockDim.x;
    int i = blockIdx.x * blockDim.x + threadIdx.x;
#pragma unroll
    for (int k = 0; k < 4; k++) {
        int idx = i + k * stride;
        if (idx < n4) {
            float4 v = src[idx];
            dst[2 * idx]     = __floats2half2_rn(v.x, v.y);
            dst[2 * idx + 1] = __floats2half2_rn(v.z, v.w);
        }
    }
}

// 4 weight tensors, each 1M floats = 262144 float4
__global__ void conv_w(const float4* __restrict__ s0, __half2* __restrict__ d0,
                       const float4* __restrict__ s1, __half2* __restrict__ d1,
                       const float4* __restrict__ s2, __half2* __restrict__ d2,
                       const float4* __restrict__ s3, __half2* __restrict__ d3)
{
    const int SEG = 262144;
    const int stride = gridDim.x * blockDim.x;
    int i = blockIdx.x * blockDim.x + threadIdx.x;
#pragma unroll
    for (int k = 0; k < 4; k++) {
        int idx = i + k * stride;
        if (idx >= 4 * SEG) continue;
        const float4* s; __half2* d;
        int seg = idx >> 18, off = idx & (SEG - 1);
        if (seg == 0) { s = s0; d = d0; }
        else if (seg == 1) { s = s1; d = d1; }
        else if (seg == 2) { s = s2; d = d2; }
        else { s = s3; d = d3; }
        float4 v = s[off];
        d[2 * off]     = __floats2half2_rn(v.x, v.y);
        d[2 * off + 1] = __floats2half2_rn(v.z, v.w);
    }
}

// ---- chunked scans: 64 chunks of 128 steps ----
__global__ void scan_pass1()
{
    const int c = blockIdx.x, h = blockIdx.y, v = threadIdx.x;
    __shared__ float a_s[128];
    a_s[v]      = g_a[(c * 128 + v) * NH + h];
    a_s[v + 64] = g_a[(c * 128 + v + 64) * NH + h];
    __syncthreads();
    const int hv = h * DH + v;
    float acc = 0.f;
#pragma unroll 4
    for (int t = 0; t < 128; t++)
        acc = fmaf(a_s[t], __half2float(g_v_h[(size_t)(c * 128 + t) * NN + hv]), acc);
    g_pav[c * NN + hv] = acc;
}

__global__ void scan_pass2a()
{
    __shared__ float pa[64 * NH];
    const int tid = threadIdx.x;
    const int c = tid >> 4, h = tid & 15;
    float s = 0.f;
    for (int i = 0; i < 128; i++) s += g_a[(c * 128 + i) * NH + h];
    pa[c * NH + h] = s;
    __syncthreads();
    if (tid < NH) {
        float acc = 0.f;
        for (int cc = 0; cc < 64; cc++) {
            float x = pa[cc * NH + tid];
            g_basea[cc * NH + tid] = acc;
            acc += x;
        }
    }
}

__global__ void scan_pass2c()
{
    const int hv = blockIdx.x * blockDim.x + threadIdx.x;
    float acc = 0.f;
    for (int c = 0; c < 64; c++) {
        float x = g_pav[c * NN + hv];
        g_bav[c * NN + hv] = acc;
        acc += x;
    }
}

__global__ void scan_pass3()
{
    const int c = blockIdx.x, h = blockIdx.y, v = threadIdx.x;
    __shared__ float a_s[128];
    __shared__ float inv_s[128];
    a_s[v]      = g_a[(c * 128 + v) * NH + h];
    a_s[v + 64] = g_a[(c * 128 + v + 64) * NH + h];
    __syncthreads();
    if (v == 0) {
        float run = g_basea[c * NH + h];
        for (int t = 0; t < 128; t++) { run += a_s[t]; inv_s[t] = run; }
    }
    __syncthreads();
    inv_s[v]      = 1.0f / inv_s[v];
    inv_s[v + 64] = 1.0f / inv_s[v + 64];
    __syncthreads();

    const int hv = h * DH + v;
    float acc = g_bav[c * NN + hv];
#pragma unroll 4
    for (int t = 0; t < 128; t++) {
        acc = fmaf(a_s[t], __half2float(g_v_h[(size_t)(c * 128 + t) * NN + hv]), acc);
        g_attn_h[(size_t)(c * 128 + t) * NN + hv] = __float2half_rn(acc * inv_s[t]);
    }
}

// ---------------------------------------------------------------------------
extern "C" void kernel_launch(void* const* d_in, const int* in_sizes, int n_in,
                              void* d_out, int out_size)
{
    const float* xs = (const float*)d_in[0];
    // d_in[1] = wq: unused (query factor cancels in sq/zq)
    const float* wk = (const float*)d_in[2];
    const float* wv = (const float*)d_in[3];
    const float* w1 = (const float*)d_in[4];
    const float* b1 = (const float*)d_in[5];
    const float* w2 = (const float*)d_in[6];
    const float* b2 = (const float*)d_in[7];
    float* out = (float*)d_out;

    __half *xs_h, *wk_h, *wv_h, *w1_h, *w2_h, *attn_h, *h1_h, *v_h;
    float *abuf;
    cudaGetSymbolAddress((void**)&xs_h, g_xs_h);
    cudaGetSymbolAddress((void**)&wk_h, g_wk_h);
    cudaGetSymbolAddress((void**)&wv_h, g_wv_h);
    cudaGetSymbolAddress((void**)&w1_h, g_w1_h);
    cudaGetSymbolAddress((void**)&w2_h, g_w2_h);
    cudaGetSymbolAddress((void**)&attn_h, g_attn_h);
    cudaGetSymbolAddress((void**)&h1_h, g_h1_h);
    cudaGetSymbolAddress((void**)&v_h, g_v_h);
    cudaGetSymbolAddress((void**)&abuf, g_a);

    cudaFuncSetAttribute(gemm_h<0>, cudaFuncAttributeMaxDynamicSharedMemorySize, SMEM_BYTES);
    cudaFuncSetAttribute(gemm_h<1>, cudaFuncAttributeMaxDynamicSharedMemorySize, SMEM_BYTES);
    cudaFuncSetAttribute(gemm_h<2>, cudaFuncAttributeMaxDynamicSharedMemorySize, SMEM_BYTES);
    cudaFuncSetAttribute(gemm_h<3>, cudaFuncAttributeMaxDynamicSharedMemorySize, SMEM_BYTES);

    // conversions (ILP=4)
    {
        int n4 = SEQ * DM / 4;                   // 2,097,152
        conv_xs<<<n4 / (256 * 4), 256>>>((const float4*)xs, (__half2*)xs_h, n4);
        conv_w<<<(4 * 262144) / (256 * 4), 256>>>(
            (const float4*)wk, (__half2*)wk_h, (const float4*)wv, (__half2*)wv_h,
            (const float4*)w1, (__half2*)w1_h, (const float4*)w2, (__half2*)w2_h);
    }

    dim3 grid(NN / 128, SEQ / 128);   // (8, 64)

    gemm_h<1><<<grid, 256, SMEM_BYTES>>>(xs_h, wk_h, nullptr, abuf);  // -> g_a fused
    gemm_h<0><<<grid, 256, SMEM_BYTES>>>(xs_h, wv_h, nullptr, v_h);   // -> g_v_h fp16

    scan_pass1<<<dim3(64, NH), DH>>>();
    scan_pass2a<<<1, 1024>>>();
    scan_pass2c<<<4, 256>>>();
    scan_pass3<<<dim3(64, NH), DH>>>();

    gemm_h<2><<<grid, 256, SMEM_BYTES>>>(attn_h, w1_h, b1, h1_h);
    gemm_h<3><<<grid, 256, SMEM_BYTES>>>(h1_h, w2_h, b2, out);
}